// round 4
// baseline (speedup 1.0000x reference)
#include <cuda_runtime.h>
#include <cuda_bf16.h>

// SAGEConv copy_u_mean, pull formulation (CSR build + gather):
//   1) zero counts/cursors  2) in-degree histogram  3) per-block exclusive scan
//   4) parallel scan of block sums  5) fill CSR buckets  6) gather-sum + mean
// Offsets are kept factored as g_off[i] (in-block exclusive) + g_bsum[i>>10]
// (block base), composed at use — no scan_add pass needed.

#define N_MAX   131072     // >= 100000
#define E_MAX   1700000    // >= 1600000
#define SCAN_B  1024
#define NBSUM   128        // N_MAX / SCAN_B

__device__ int g_count[N_MAX];
__device__ int g_off[N_MAX];      // in-block exclusive prefix
__device__ int g_cursor[N_MAX];   // per-node fill counter (starts at 0)
__device__ int g_esrc[E_MAX];
__device__ int g_bsum[NBSUM];     // exclusive block bases after k_scan_sums

// ---- K0: zero counts + cursors ----
__global__ void k_zero(int n) {
    int i = blockIdx.x * blockDim.x + threadIdx.x;
    if (i < n) { g_count[i] = 0; g_cursor[i] = 0; }
}

// ---- K1: in-degree histogram, 4 edges/thread ----
__global__ void k_hist(const int* __restrict__ dst, int E) {
    int base = (blockIdx.x * blockDim.x + threadIdx.x) * 4;
    if (base + 3 < E) {
        int4 d = *(const int4*)(dst + base);
        atomicAdd(&g_count[d.x], 1);
        atomicAdd(&g_count[d.y], 1);
        atomicAdd(&g_count[d.z], 1);
        atomicAdd(&g_count[d.w], 1);
    } else {
        for (int e = base; e < E; e++) atomicAdd(&g_count[dst[e]], 1);
    }
}

// ---- K2a: per-block exclusive scan (Hillis-Steele in smem) ----
__global__ void k_scan_block(int n) {
    __shared__ int sh[SCAN_B];
    int tid = threadIdx.x;
    int i = blockIdx.x * SCAN_B + tid;
    int v = (i < n) ? g_count[i] : 0;
    sh[tid] = v;
    __syncthreads();
    #pragma unroll
    for (int off = 1; off < SCAN_B; off <<= 1) {
        int t = (tid >= off) ? sh[tid - off] : 0;
        __syncthreads();
        sh[tid] += t;
        __syncthreads();
    }
    if (i < n) g_off[i] = sh[tid] - v;              // exclusive (in-block)
    if (tid == SCAN_B - 1) g_bsum[blockIdx.x] = sh[tid];
}

// ---- K2b: parallel exclusive scan of <=128 block sums (one block) ----
__global__ void k_scan_sums(int nblocks) {
    __shared__ int sh[NBSUM];
    int t = threadIdx.x;
    int v = (t < nblocks) ? g_bsum[t] : 0;
    sh[t] = v;
    __syncthreads();
    #pragma unroll
    for (int off = 1; off < NBSUM; off <<= 1) {
        int u = (t >= off) ? sh[t - off] : 0;
        __syncthreads();
        sh[t] += u;
        __syncthreads();
    }
    if (t < nblocks) g_bsum[t] = sh[t] - v;          // exclusive
}

// ---- K3: scatter src ids into CSR buckets, 4 edges/thread ----
__device__ __forceinline__ void fill_one(int s, int d) {
    int pos = g_off[d] + g_bsum[d >> 10] + atomicAdd(&g_cursor[d], 1);
    g_esrc[pos] = s;
}
__global__ void k_fill(const int* __restrict__ src,
                       const int* __restrict__ dst, int E) {
    int base = (blockIdx.x * blockDim.x + threadIdx.x) * 4;
    if (base + 3 < E) {
        int4 s = *(const int4*)(src + base);
        int4 d = *(const int4*)(dst + base);
        fill_one(s.x, d.x);
        fill_one(s.y, d.y);
        fill_one(s.z, d.z);
        fill_one(s.w, d.w);
    } else {
        for (int e = base; e < E; e++) fill_one(src[e], dst[e]);
    }
}

// ---- K4: pull gather-sum + mean. 8 threads per node (one float4 quad each) ----
__global__ void k_gather(const float4* __restrict__ x4,
                         float4* __restrict__ out4,
                         int n_nodes) {
    unsigned int t = blockIdx.x * blockDim.x + threadIdx.x;
    unsigned int node = t >> 3;
    unsigned int q = t & 7;
    if (node >= (unsigned int)n_nodes) return;

    int beg = g_off[node] + g_bsum[node >> 10];
    int cnt = g_count[node];
    int end = beg + cnt;

    float4 acc = make_float4(0.f, 0.f, 0.f, 0.f);
    int i = beg;
    // unroll-by-4: 4 outstanding float4 loads hide L2 latency
    for (; i + 3 < end; i += 4) {
        int s0 = g_esrc[i];
        int s1 = g_esrc[i + 1];
        int s2 = g_esrc[i + 2];
        int s3 = g_esrc[i + 3];
        float4 v0 = x4[(size_t)s0 * 8 + q];
        float4 v1 = x4[(size_t)s1 * 8 + q];
        float4 v2 = x4[(size_t)s2 * 8 + q];
        float4 v3 = x4[(size_t)s3 * 8 + q];
        acc.x += (v0.x + v1.x) + (v2.x + v3.x);
        acc.y += (v0.y + v1.y) + (v2.y + v3.y);
        acc.z += (v0.z + v1.z) + (v2.z + v3.z);
        acc.w += (v0.w + v1.w) + (v2.w + v3.w);
    }
    for (; i < end; i++) {
        int s = g_esrc[i];
        float4 v = x4[(size_t)s * 8 + q];
        acc.x += v.x; acc.y += v.y; acc.z += v.z; acc.w += v.w;
    }

    float inv = 1.0f / fmaxf((float)cnt, 1.0f);
    acc.x *= inv; acc.y *= inv; acc.z *= inv; acc.w *= inv;
    out4[(size_t)node * 8 + q] = acc;
}

extern "C" void kernel_launch(void* const* d_in, const int* in_sizes, int n_in,
                              void* d_out, int out_size) {
    const float* x   = (const float*)d_in[0];
    const int*   src = (const int*)d_in[1];
    const int*   dst = (const int*)d_in[2];
    float* out = (float*)d_out;

    int n_nodes = in_sizes[0] / 32;
    int E = in_sizes[1];

    const int TPB = 256;
    int nb_nodes = (n_nodes + TPB - 1) / TPB;
    int nb_edge4 = ((E + 3) / 4 + TPB - 1) / TPB;
    int nb_scan  = (n_nodes + SCAN_B - 1) / SCAN_B;

    k_zero<<<nb_nodes, TPB>>>(n_nodes);
    k_hist<<<nb_edge4, TPB>>>(dst, E);
    k_scan_block<<<nb_scan, SCAN_B>>>(n_nodes);
    k_scan_sums<<<1, NBSUM>>>(nb_scan);
    k_fill<<<nb_edge4, TPB>>>(src, dst, E);

    unsigned int gtotal = (unsigned int)n_nodes * 8u;
    unsigned int gb = (gtotal + TPB - 1) / TPB;
    k_gather<<<gb, TPB>>>((const float4*)x, (float4*)out, n_nodes);
}